// round 4
// baseline (speedup 1.0000x reference)
#include <cuda_runtime.h>
#include <cstdint>

#define D       128
#define H       64
#define ALPHA   0.2f
#define LN_EPS  1e-5f
#define MAXN    131072
#define MAXE    1048576

// CSR scratch (device globals: allocation-free per harness rules)
__device__ int g_rowptr[MAXN + 1];
__device__ int g_cursor[MAXN];
__device__ int g_csr[MAXE];

__device__ __forceinline__ float2 ffma2(float2 a, float2 b, float2 c) {
    unsigned long long au = *reinterpret_cast<unsigned long long*>(&a);
    unsigned long long bu = *reinterpret_cast<unsigned long long*>(&b);
    unsigned long long cu = *reinterpret_cast<unsigned long long*>(&c);
    unsigned long long du;
    asm("fma.rn.f32x2 %0, %1, %2, %3;" : "=l"(du) : "l"(au), "l"(bu), "l"(cu));
    return *reinterpret_cast<float2*>(&du);
}

__global__ void k_zero_cnt(int N) {
    int i = blockIdx.x * blockDim.x + threadIdx.x;
    if (i < N) g_cursor[i] = 0;
}

// Degree histogram: int atomics, spread addresses -> near LSU floor.
__global__ void k_count(const int* __restrict__ ei, int E, int N) {
    int e = blockIdx.x * blockDim.x + threadIdx.x;
    if (e >= E) return;
    int dst = min(max(ei[E + e], 0), N - 1);
    atomicAdd(&g_cursor[dst], 1);
}

// Single-block exclusive scan of degrees -> row_ptr; reset cursor to row starts.
__global__ void __launch_bounds__(1024) k_scan(int N, int E) {
    __shared__ int warp_sums[32];
    int t = threadIdx.x;
    int chunk = (N + 1023) >> 10;
    int s = t * chunk, en = min(s + chunk, N);
    int sum = 0;
    for (int i = s; i < en; i++) sum += g_cursor[i];
    // inclusive warp scan
    int lane = t & 31, w = t >> 5;
    int v = sum;
    #pragma unroll
    for (int o = 1; o < 32; o <<= 1) {
        int u = __shfl_up_sync(0xffffffffu, v, o);
        if (lane >= o) v += u;
    }
    if (lane == 31) warp_sums[w] = v;
    __syncthreads();
    if (w == 0) {
        int wv = (lane < 32) ? warp_sums[lane] : 0;
        #pragma unroll
        for (int o = 1; o < 32; o <<= 1) {
            int u = __shfl_up_sync(0xffffffffu, wv, o);
            if (lane >= o) wv += u;
        }
        warp_sums[lane] = wv;
    }
    __syncthreads();
    int excl = v - sum + (w > 0 ? warp_sums[w - 1] : 0);
    int run = excl;
    for (int i = s; i < en; i++) {
        int c = g_cursor[i];
        g_rowptr[i] = run;
        g_cursor[i] = run;
        run += c;
    }
    if (t == 0) g_rowptr[N] = E;
}

// Fill CSR: pos = cursor[dst]++; csr[pos] = src.
__global__ void k_fill(const int* __restrict__ ei, int E, int N) {
    int e = blockIdx.x * blockDim.x + threadIdx.x;
    if (e >= E) return;
    int src = min(max(ei[e], 0), N - 1);
    int dst = min(max(ei[E + e], 0), N - 1);
    int pos = atomicAdd(&g_cursor[dst], 1);
    g_csr[pos] = src;
}

// Fused node kernel: CSR neighbor gather -> local_mean + tanh(||x-lm||) + MLP
// (f32x2 packed, 4 nodes/warp) + residual + LayerNorm. Weights in shared,
// persistent grid.
__global__ void __launch_bounds__(256, 2) k_nodes(
    const float* __restrict__ x,
    const float* __restrict__ W1, const float* __restrict__ b1,
    const float* __restrict__ W2, const float* __restrict__ b2,
    const float* __restrict__ gamma, const float* __restrict__ beta,
    float* __restrict__ out, int N)
{
    extern __shared__ float smem[];
    float* sW1 = smem;                 // 128*64
    float* sW2 = sW1 + D * H;          // 64*128
    float* sb1 = sW2 + H * D;          // 64
    float* sb2 = sb1 + H;              // 128
    float* sg  = sb2 + D;              // 128
    float* sbt = sg + D;               // 128
    float* sxT = sbt + D;              // 8 warps * 128 * 4  (x transposed [k][node])
    float* shT = sxT + 8 * D * 4;      // 8 warps * 64 * 4   (hidden transposed)

    int tid = threadIdx.x;
    for (int i = tid; i < D * H; i += 256) sW1[i] = W1[i];
    for (int i = tid; i < H * D; i += 256) sW2[i] = W2[i];
    if (tid < H) sb1[tid] = b1[tid];
    if (tid < D) { sb2[tid] = b2[tid]; sg[tid] = gamma[tid]; sbt[tid] = beta[tid]; }
    __syncthreads();

    int w = tid >> 5, lane = tid & 31;
    int nn = lane >> 3, c = lane & 7;     // lane group: 4 nodes x 8 chunk-lanes
    float* myxT = sxT + w * (D * 4);
    float* myhT = shT + w * (H * 4);

    for (int base = blockIdx.x * 32 + w * 4; base < N; base += gridDim.x * 32) {
        // ---- phase 1: load x row, gather+sum neighbors via CSR, feature_diff;
        //      stage x transposed [k][node] ----
        int node = base + nn;
        bool valid = node < N;
        const float4* xrow = reinterpret_cast<const float4*>(x + (size_t)node * D);
        float4 z = make_float4(0.f, 0.f, 0.f, 0.f);
        float4 xv0 = z, xv1 = z, xv2 = z, xv3 = z;
        int rs = 0, re = 0;
        if (valid) {
            xv0 = xrow[c]; xv1 = xrow[c + 8]; xv2 = xrow[c + 16]; xv3 = xrow[c + 24];
            rs = g_rowptr[node]; re = g_rowptr[node + 1];
        }
        float4 a0 = z, a1 = z, a2 = z, a3 = z;
        for (int e2 = rs; e2 < re; e2++) {
            int src = g_csr[e2];
            const float4* srow = reinterpret_cast<const float4*>(x + (size_t)src * D);
            float4 s0 = srow[c], s1 = srow[c + 8], s2 = srow[c + 16], s3 = srow[c + 24];
            a0.x += s0.x; a0.y += s0.y; a0.z += s0.z; a0.w += s0.w;
            a1.x += s1.x; a1.y += s1.y; a1.z += s1.z; a1.w += s1.w;
            a2.x += s2.x; a2.y += s2.y; a2.z += s2.z; a2.w += s2.w;
            a3.x += s3.x; a3.y += s3.y; a3.z += s3.z; a3.w += s3.w;
        }
        float inv = 1.0f / fmaxf((float)(re - rs), 1.0f);
        float ss = 0.f;
        {
            float dx, dy, dz, dw;
            dx = xv0.x - a0.x * inv; dy = xv0.y - a0.y * inv;
            dz = xv0.z - a0.z * inv; dw = xv0.w - a0.w * inv;
            ss += dx * dx + dy * dy + dz * dz + dw * dw;
            dx = xv1.x - a1.x * inv; dy = xv1.y - a1.y * inv;
            dz = xv1.z - a1.z * inv; dw = xv1.w - a1.w * inv;
            ss += dx * dx + dy * dy + dz * dz + dw * dw;
            dx = xv2.x - a2.x * inv; dy = xv2.y - a2.y * inv;
            dz = xv2.z - a2.z * inv; dw = xv2.w - a2.w * inv;
            ss += dx * dx + dy * dy + dz * dz + dw * dw;
            dx = xv3.x - a3.x * inv; dy = xv3.y - a3.y * inv;
            dz = xv3.z - a3.z * inv; dw = xv3.w - a3.w * inv;
            ss += dx * dx + dy * dy + dz * dz + dw * dw;
        }
        ss += __shfl_xor_sync(0xffffffffu, ss, 1);
        ss += __shfl_xor_sync(0xffffffffu, ss, 2);
        ss += __shfl_xor_sync(0xffffffffu, ss, 4);
        float fd = tanhf(sqrtf(ss));
        float fda0 = __shfl_sync(0xffffffffu, fd, 0);
        float fda1 = __shfl_sync(0xffffffffu, fd, 8);
        float fda2 = __shfl_sync(0xffffffffu, fd, 16);
        float fda3 = __shfl_sync(0xffffffffu, fd, 24);
        // stage x transposed
        myxT[(4 * c + 0) * 4 + nn] = xv0.x;
        myxT[(4 * c + 1) * 4 + nn] = xv0.y;
        myxT[(4 * c + 2) * 4 + nn] = xv0.z;
        myxT[(4 * c + 3) * 4 + nn] = xv0.w;
        myxT[(4 * (c + 8) + 0) * 4 + nn] = xv1.x;
        myxT[(4 * (c + 8) + 1) * 4 + nn] = xv1.y;
        myxT[(4 * (c + 8) + 2) * 4 + nn] = xv1.z;
        myxT[(4 * (c + 8) + 3) * 4 + nn] = xv1.w;
        myxT[(4 * (c + 16) + 0) * 4 + nn] = xv2.x;
        myxT[(4 * (c + 16) + 1) * 4 + nn] = xv2.y;
        myxT[(4 * (c + 16) + 2) * 4 + nn] = xv2.z;
        myxT[(4 * (c + 16) + 3) * 4 + nn] = xv2.w;
        myxT[(4 * (c + 24) + 0) * 4 + nn] = xv3.x;
        myxT[(4 * (c + 24) + 1) * 4 + nn] = xv3.y;
        myxT[(4 * (c + 24) + 2) * 4 + nn] = xv3.z;
        myxT[(4 * (c + 24) + 3) * 4 + nn] = xv3.w;
        __syncwarp();

        // ---- GEMM1: hidden = relu(x@W1 + b1); lane owns cols 2*lane,2*lane+1 ----
        float2 bini = make_float2(sb1[2 * lane], sb1[2 * lane + 1]);
        float2 g1a0 = bini, g1a1 = bini, g1a2 = bini, g1a3 = bini;
        const float2* w1p = reinterpret_cast<const float2*>(sW1) + lane;
        #pragma unroll 8
        for (int k = 0; k < D; k++) {
            float2 wv = w1p[k * (H / 2)];
            float4 xb = reinterpret_cast<const float4*>(myxT)[k];  // broadcast: 4 nodes
            g1a0 = ffma2(make_float2(xb.x, xb.x), wv, g1a0);
            g1a1 = ffma2(make_float2(xb.y, xb.y), wv, g1a1);
            g1a2 = ffma2(make_float2(xb.z, xb.z), wv, g1a2);
            g1a3 = ffma2(make_float2(xb.w, xb.w), wv, g1a3);
        }
        myhT[(2 * lane) * 4 + 0] = fmaxf(g1a0.x, 0.f);
        myhT[(2 * lane) * 4 + 1] = fmaxf(g1a1.x, 0.f);
        myhT[(2 * lane) * 4 + 2] = fmaxf(g1a2.x, 0.f);
        myhT[(2 * lane) * 4 + 3] = fmaxf(g1a3.x, 0.f);
        myhT[(2 * lane + 1) * 4 + 0] = fmaxf(g1a0.y, 0.f);
        myhT[(2 * lane + 1) * 4 + 1] = fmaxf(g1a1.y, 0.f);
        myhT[(2 * lane + 1) * 4 + 2] = fmaxf(g1a2.y, 0.f);
        myhT[(2 * lane + 1) * 4 + 3] = fmaxf(g1a3.y, 0.f);
        __syncwarp();

        // ---- GEMM2: out = hidden@W2 + b2; lane owns cols 4*lane..4*lane+3 ----
        float4 b2v = reinterpret_cast<const float4*>(sb2)[lane];
        float2 o0a = make_float2(b2v.x, b2v.y), o0b = make_float2(b2v.z, b2v.w);
        float2 o1a = o0a, o1b = o0b, o2a = o0a, o2b = o0b, o3a = o0a, o3b = o0b;
        #pragma unroll 8
        for (int j = 0; j < H; j++) {
            float4 wv = reinterpret_cast<const float4*>(sW2 + j * D)[lane];
            float4 hb = reinterpret_cast<const float4*>(myhT)[j];  // broadcast: 4 nodes
            float2 wlo = make_float2(wv.x, wv.y), whi = make_float2(wv.z, wv.w);
            o0a = ffma2(make_float2(hb.x, hb.x), wlo, o0a);
            o0b = ffma2(make_float2(hb.x, hb.x), whi, o0b);
            o1a = ffma2(make_float2(hb.y, hb.y), wlo, o1a);
            o1b = ffma2(make_float2(hb.y, hb.y), whi, o1b);
            o2a = ffma2(make_float2(hb.z, hb.z), wlo, o2a);
            o2b = ffma2(make_float2(hb.z, hb.z), whi, o2b);
            o3a = ffma2(make_float2(hb.w, hb.w), wlo, o3a);
            o3b = ffma2(make_float2(hb.w, hb.w), whi, o3b);
        }

        // ---- epilogue: residual + LayerNorm, one node at a time ----
        float4 g4  = reinterpret_cast<const float4*>(sg)[lane];
        float4 be4 = reinterpret_cast<const float4*>(sbt)[lane];
        #pragma unroll
        for (int q = 0; q < 4; q++) {
            int nd = base + q;
            if (nd >= N) break;
            float fdq = (q == 0) ? fda0 : (q == 1) ? fda1 : (q == 2) ? fda2 : fda3;
            float2 oa = (q == 0) ? o0a : (q == 1) ? o1a : (q == 2) ? o2a : o3a;
            float2 ob = (q == 0) ? o0b : (q == 1) ? o1b : (q == 2) ? o2b : o3b;
            float4 xq = reinterpret_cast<const float4*>(x + (size_t)nd * D)[lane];
            float af = ALPHA * fdq;
            float4 hv;
            hv.x = xq.x + af * oa.x;
            hv.y = xq.y + af * oa.y;
            hv.z = xq.z + af * ob.x;
            hv.w = xq.w + af * ob.y;
            float s  = hv.x + hv.y + hv.z + hv.w;
            float s2 = hv.x * hv.x + hv.y * hv.y + hv.z * hv.z + hv.w * hv.w;
            #pragma unroll
            for (int o = 16; o > 0; o >>= 1) {
                s  += __shfl_xor_sync(0xffffffffu, s, o);
                s2 += __shfl_xor_sync(0xffffffffu, s2, o);
            }
            float mu  = s * (1.0f / 128.0f);
            float var = s2 * (1.0f / 128.0f) - mu * mu;
            float rs2 = rsqrtf(var + LN_EPS);
            float4 y;
            y.x = (hv.x - mu) * rs2 * g4.x + be4.x;
            y.y = (hv.y - mu) * rs2 * g4.y + be4.y;
            y.z = (hv.z - mu) * rs2 * g4.z + be4.z;
            y.w = (hv.w - mu) * rs2 * g4.w + be4.w;
            reinterpret_cast<float4*>(out + (size_t)nd * D)[lane] = y;
        }
        __syncwarp();
    }
}

extern "C" void kernel_launch(void* const* d_in, const int* in_sizes, int n_in,
                              void* d_out, int out_size) {
    const float* x        = (const float*)d_in[0];
    const int*   ei       = (const int*)d_in[1];   // int32: JAX demotes int64
    const float* W1       = (const float*)d_in[2];
    const float* b1       = (const float*)d_in[3];
    const float* W2       = (const float*)d_in[4];
    const float* b2       = (const float*)d_in[5];
    const float* gamma    = (const float*)d_in[6];
    const float* beta     = (const float*)d_in[7];
    float* out            = (float*)d_out;

    int N = in_sizes[0] / D;
    int E = in_sizes[1] / 2;

    // CSR build: zero counters -> histogram -> scan -> fill
    k_zero_cnt<<<(N + 255) / 256, 256>>>(N);
    k_count<<<(E + 255) / 256, 256>>>(ei, E, N);
    k_scan<<<1, 1024>>>(N, E);
    k_fill<<<(E + 255) / 256, 256>>>(ei, E, N);

    // fused node pipeline
    {
        size_t smem_bytes = (size_t)(D * H + H * D + H + D + D + D + 8 * D * 4 + 8 * H * 4) * sizeof(float);
        cudaFuncSetAttribute(k_nodes, cudaFuncAttributeMaxDynamicSharedMemorySize, (int)smem_bytes);
        k_nodes<<<296, 256, smem_bytes>>>(x, W1, b1, W2, b2, gamma, beta, out, N);
    }
}